// round 13
// baseline (speedup 1.0000x reference)
#include <cuda_runtime.h>
#include <cuda_fp16.h>
#include <cstdint>

#define BB   8
#define LL   8192
#define DIM  512
#define NH   8
#define DH   64
#define KS   13
#define NS   6
#define DIL  2

// ---------------------------------------------------------------------------
// Device scratch (static only)
// ---------------------------------------------------------------------------
__device__ float g_q[(size_t)BB * NH * LL * DH];
__device__ float g_k[(size_t)BB * NH * LL * DH];
__device__ float g_v[(size_t)BB * NH * LL * DH];
__device__ __half g_ah[(size_t)BB * LL * DIM];   // hidden fp16 [M,K]
__device__ __half g_wh[3][DIM * DIM];            // W^T fp16  [N,K]

// ---------------------------------------------------------------------------
// Baseline-PTX helpers
// ---------------------------------------------------------------------------
__device__ __forceinline__ uint32_t smem_u32(const void* p) {
    uint32_t a;
    asm("{ .reg .u64 t; cvta.to.shared.u64 t, %1; cvt.u32.u64 %0, t; }" : "=r"(a) : "l"(p));
    return a;
}
__device__ __forceinline__ void cp_async16(uint32_t saddr, const void* gptr) {
    asm volatile("cp.async.cg.shared.global [%0], [%1], 16;"
                 :: "r"(saddr), "l"(__cvta_generic_to_global(gptr)) : "memory");
}
#define CP_COMMIT() asm volatile("cp.async.commit_group;" ::: "memory")
#define CP_WAIT(n)  asm volatile("cp.async.wait_group %0;" :: "n"(n) : "memory")

__device__ __forceinline__ void ldsm_x4(uint32_t* r, uint32_t addr) {
    asm volatile("ldmatrix.sync.aligned.m8n8.x4.shared.b16 {%0,%1,%2,%3}, [%4];"
                 : "=r"(r[0]), "=r"(r[1]), "=r"(r[2]), "=r"(r[3]) : "r"(addr));
}
__device__ __forceinline__ void ldsm_x2(uint32_t* r, uint32_t addr) {
    asm volatile("ldmatrix.sync.aligned.m8n8.x2.shared.b16 {%0,%1}, [%2];"
                 : "=r"(r[0]), "=r"(r[1]) : "r"(addr));
}
__device__ __forceinline__ void mma16816(float* c, const uint32_t* a, const uint32_t* b) {
    asm volatile("mma.sync.aligned.m16n8k16.row.col.f32.f16.f16.f32 "
                 "{%0,%1,%2,%3}, {%4,%5,%6,%7}, {%8,%9}, {%0,%1,%2,%3};"
                 : "+f"(c[0]), "+f"(c[1]), "+f"(c[2]), "+f"(c[3])
                 : "r"(a[0]), "r"(a[1]), "r"(a[2]), "r"(a[3]), "r"(b[0]), "r"(b[1]));
}

// ---------------------------------------------------------------------------
// Convert hidden states fp32 -> fp16
// ---------------------------------------------------------------------------
__global__ void convert_a_kernel(const float* __restrict__ A) {
    size_t i = ((size_t)blockIdx.x * 256 + threadIdx.x) * 4;
    float4 x = *(const float4*)(A + i);
    union { __half b[4]; uint2 u; } ph;
    ph.b[0] = __float2half_rn(x.x);
    ph.b[1] = __float2half_rn(x.y);
    ph.b[2] = __float2half_rn(x.z);
    ph.b[3] = __float2half_rn(x.w);
    *(uint2*)(g_ah + i) = ph.u;
}

// ---------------------------------------------------------------------------
// Transpose W [K,N] -> W^T [N,K] fp16
// ---------------------------------------------------------------------------
__global__ void convert_w_kernel(const float* __restrict__ Wq,
                                 const float* __restrict__ Wk,
                                 const float* __restrict__ Wv) {
    const int z = blockIdx.z;
    const float* W = (z == 0) ? Wq : ((z == 1) ? Wk : Wv);
    __shared__ float t[32][33];
    const int n0 = blockIdx.x * 32, k0 = blockIdx.y * 32;
    #pragma unroll
    for (int j = 0; j < 32; j += 8)
        t[threadIdx.y + j][threadIdx.x] = W[(size_t)(k0 + threadIdx.y + j) * DIM + n0 + threadIdx.x];
    __syncthreads();
    #pragma unroll
    for (int j = 0; j < 32; j += 8) {
        float v = t[threadIdx.x][threadIdx.y + j];
        size_t o = (size_t)(n0 + threadIdx.y + j) * DIM + k0 + threadIdx.x;
        g_wh[z][o] = __float2half_rn(v);
    }
}

// ---------------------------------------------------------------------------
// HMMA fp16 GEMM (1-term): unchanged from round 12 (245-280us)
// ---------------------------------------------------------------------------
#define TILE_B   16384
#define STAGE_B  (2 * TILE_B)     // 32KB
#define NSTG     3
#define KSTAGES  8                // 512 / 64

__global__ void __launch_bounds__(256)
qkv_mma_gemm(const float* __restrict__ bq, const float* __restrict__ bk,
             const float* __restrict__ bv)
{
    extern __shared__ __align__(1024) char dsm[];
    __shared__ float s_bias[128];

    const int tid  = threadIdx.x;
    const int wid  = tid >> 5;
    const int lane = tid & 31;
    const int wm   = wid >> 2;
    const int wn   = wid & 3;
    const int nt   = blockIdx.x & 3;
    const int z    = blockIdx.x >> 2;
    const int mt   = blockIdx.y;

    const uint32_t sbase = smem_u32(dsm);

    const float* bias = (z == 0) ? bq : ((z == 1) ? bk : bv);
    const float scale = (z == 0) ? 0.125f : 1.0f;
    float* outp       = (z == 0) ? g_q : ((z == 1) ? g_k : g_v);
    const __half* srcs[2] = { g_ah + (size_t)mt * 128 * DIM,
                              g_wh[z] + (size_t)nt * 128 * DIM };

    if (tid < 128) s_bias[tid] = bias[nt * 128 + tid];

    auto load_stage = [&](int kt, int buf) {
        const uint32_t sb = sbase + (uint32_t)buf * STAGE_B;
        #pragma unroll
        for (int tile = 0; tile < 2; ++tile) {
            const __half* src = srcs[tile] + kt * 64;
            #pragma unroll
            for (int it = 0; it < 4; ++it) {
                const int c = it * 256 + tid;
                const int r = c >> 3, j = c & 7;
                const uint32_t soff = sb + (uint32_t)tile * TILE_B +
                                      (uint32_t)r * 128 + (uint32_t)((j ^ (r & 7)) << 4);
                cp_async16(soff, src + (size_t)r * DIM + j * 8);
            }
        }
        CP_COMMIT();
    };

    float acc[4][4][4];
    #pragma unroll
    for (int mi = 0; mi < 4; ++mi)
        #pragma unroll
        for (int ni = 0; ni < 4; ++ni)
            #pragma unroll
            for (int q = 0; q < 4; ++q) acc[mi][ni][q] = 0.f;

    load_stage(0, 0);
    load_stage(1, 1);

    for (int kt = 0; kt < KSTAGES; ++kt) {
        if (kt < KSTAGES - 1) { CP_WAIT(1); } else { CP_WAIT(0); }
        __syncthreads();
        if (kt + 2 < KSTAGES) load_stage(kt + 2, (kt + 2) % NSTG);

        const uint32_t sb = sbase + (uint32_t)(kt % NSTG) * STAGE_B;
        const uint32_t aH = sb, bH = sb + TILE_B;

        const int arow = wm * 64 + (lane & 15);
        const int ahalf = lane >> 4;
        const int brow = wn * 32 + (lane & 7);
        const int bhalf = (lane >> 3) & 1;

        #pragma unroll
        for (int ks = 0; ks < 4; ++ks) {
            uint32_t bhf[4][2];
            #pragma unroll
            for (int ni = 0; ni < 4; ++ni) {
                const int r = brow + ni * 8;
                const int j = ks * 2 + bhalf;
                const uint32_t off = (uint32_t)r * 128 + (uint32_t)((j ^ (r & 7)) << 4);
                ldsm_x2(bhf[ni], bH + off);
            }
            #pragma unroll
            for (int mi = 0; mi < 4; ++mi) {
                const int r = arow + mi * 16;
                const int j = ks * 2 + ahalf;
                const uint32_t off = (uint32_t)r * 128 + (uint32_t)((j ^ (r & 7)) << 4);
                uint32_t ahf[4];
                ldsm_x4(ahf, aH + off);
                #pragma unroll
                for (int ni = 0; ni < 4; ++ni)
                    mma16816(acc[mi][ni], ahf, bhf[ni]);
            }
        }
    }

    const int g = lane >> 2, tig = lane & 3;
    #pragma unroll
    for (int mi = 0; mi < 4; ++mi) {
        #pragma unroll
        for (int half = 0; half < 2; ++half) {
            const int m = mt * 128 + wm * 64 + mi * 16 + g + half * 8;
            const int b = m >> 13;
            const int l = m & (LL - 1);
            #pragma unroll
            for (int ni = 0; ni < 4; ++ni) {
                const int nl = wn * 32 + ni * 8 + 2 * tig;
                const int n  = nt * 128 + nl;
                const int h  = n >> 6, d = n & 63;
                float2 r2;
                r2.x = (acc[mi][ni][half * 2 + 0] + s_bias[nl + 0]) * scale;
                r2.y = (acc[mi][ni][half * 2 + 1] + s_bias[nl + 1]) * scale;
                *(float2*)&outp[(((size_t)b * NH + h) * LL + l) * DH + d] = r2;
            }
        }
    }
}

// ---------------------------------------------------------------------------
// NA1D attention — 2 queries (i, i+2) per thread, sharing 12/13 K & V rows.
// 256 queries per CTA, 128 threads. Even/odd rows stored in separate smem
// regions (both stride 68 words; odd base 9540 words == 4 mod 32) so the
// phase-lane row pattern {C,C+1,C+4,C+5,...} is bank-conflict-free.
// ---------------------------------------------------------------------------
#define QT2   256
#define EVS   68        // word stride within each parity region
#define ODB   9540      // word base of odd-row region (== 4 mod 32)
#define SMW   (ODB + 140 * EVS)   // 19060 words = 76240 bytes

#define DOT4(acc, q4, k4) \
    acc = fmaf((q4).x,(k4).x, fmaf((q4).y,(k4).y, fmaf((q4).z,(k4).z, fmaf((q4).w,(k4).w,(acc)))))

__device__ __forceinline__ void na_ws_ps(int i, int& ws, int& ps) {
    if (i < NS * DIL)            { ws = i & 1;                      ps = (KS - 1) - (i >> 1); }
    else if (i + NS * DIL >= LL) { ws = LL - KS * DIL + (i & 1);    ps = (LL - 1 - i) >> 1;   }
    else                         { ws = i - NS * DIL;               ps = NS;                  }
}

__global__ void __launch_bounds__(128)
na1d_kernel(const float* __restrict__ rpb, float* __restrict__ out)
{
    extern __shared__ float sm[];
    __shared__ float s_rpb[2 * KS - 1];

    const int tid = threadIdx.x;
    const int bh  = blockIdx.y;
    const int b   = bh >> 3;
    const int h   = bh & 7;
    const int l0  = blockIdx.x * QT2;
    const int i0  = l0 + 4 * (tid >> 1) + (tid & 1);
    const int i1  = i0 + 2;

    if (tid < 2 * KS - 1) s_rpb[tid] = rpb[h * (2 * KS - 1) + tid];

    int ws0, ps0, ws1, ps1;
    na_ws_ps(i0, ws0, ps0);
    na_ws_ps(i1, ws1, ps1);

    const int lo = (l0 >= NS * DIL) ? (l0 - NS * DIL) : 0;
    const int himax = l0 + QT2 - 1 + NS * DIL;
    const int hi = (himax <= LL - 1) ? himax : (LL - 1);
    const int nrows = hi - lo + 1;
    const size_t base = (size_t)bh * LL * DH;

    auto rowptr = [&](int r) -> const float4* {
        return (const float4*)(sm + ((r & 1) ? ODB : 0) + (r >> 1) * EVS);
    };

    // ---- stage K tile ----
    {
        const float4* src = (const float4*)(g_k + base + (size_t)lo * DH);
        const int n4 = nrows * 16;
        for (int tt = tid; tt < n4; tt += 128) {
            const int r = tt >> 4, c = tt & 15;
            float* w = sm + ((r & 1) ? ODB : 0) + (r >> 1) * EVS + c * 4;
            *(float4*)w = src[tt];
        }
    }

    // ---- q0, q1 into registers ----
    float4 q0[16], q1[16];
    {
        const float4* p0 = (const float4*)(g_q + base + (size_t)i0 * DH);
        const float4* p1 = (const float4*)(g_q + base + (size_t)i1 * DH);
        #pragma unroll
        for (int d = 0; d < 16; ++d) { q0[d] = p0[d]; q1[d] = p1[d]; }
    }
    __syncthreads();

    // ---- scores ----
    float s0[KS], s1[KS];
    const bool shp = (ws1 == ws0 + 2);
    if (shp) {
        const int r0l = ws0 - lo;
        #pragma unroll
        for (int jj = 0; jj < 14; ++jj) {
            const float4* kr = rowptr(r0l + 2 * jj);
            float a0 = 0.f, a1 = 0.f;
            #pragma unroll
            for (int d = 0; d < 16; ++d) {
                const float4 k4 = kr[d];
                DOT4(a0, q0[d], k4);
                DOT4(a1, q1[d], k4);
            }
            if (jj < 13) s0[jj] = a0;
            if (jj >= 1) s1[jj - 1] = a1;
        }
    } else {
        const int rA = ws0 - lo, rB = ws1 - lo;
        #pragma unroll
        for (int j = 0; j < KS; ++j) {
            const float4* kr = rowptr(rA + 2 * j);
            float a = 0.f;
            #pragma unroll
            for (int d = 0; d < 16; ++d) { const float4 k4 = kr[d]; DOT4(a, q0[d], k4); }
            s0[j] = a;
        }
        #pragma unroll
        for (int j = 0; j < KS; ++j) {
            const float4* kr = rowptr(rB + 2 * j);
            float a = 0.f;
            #pragma unroll
            for (int d = 0; d < 16; ++d) { const float4 k4 = kr[d]; DOT4(a, q1[d], k4); }
            s1[j] = a;
        }
    }

    // ---- softmax (both queries) ----
    #pragma unroll
    for (int j = 0; j < KS; ++j) { s0[j] += s_rpb[ps0 + j]; s1[j] += s_rpb[ps1 + j]; }
    float mx0 = s0[0], mx1 = s1[0];
    #pragma unroll
    for (int j = 1; j < KS; ++j) { mx0 = fmaxf(mx0, s0[j]); mx1 = fmaxf(mx1, s1[j]); }
    float sum0 = 0.f, sum1 = 0.f;
    #pragma unroll
    for (int j = 0; j < KS; ++j) {
        s0[j] = __expf(s0[j] - mx0); sum0 += s0[j];
        s1[j] = __expf(s1[j] - mx1); sum1 += s1[j];
    }
    const float rinv0 = 1.f / sum0, rinv1 = 1.f / sum1;

    __syncthreads();

    // ---- stage V tile (same buffer) ----
    {
        const float4* src = (const float4*)(g_v + base + (size_t)lo * DH);
        const int n4 = nrows * 16;
        for (int tt = tid; tt < n4; tt += 128) {
            const int r = tt >> 4, c = tt & 15;
            float* w = sm + ((r & 1) ? ODB : 0) + (r >> 1) * EVS + c * 4;
            *(float4*)w = src[tt];
        }
    }
    __syncthreads();

    // ---- weighted V accumulation ----
    float4 o0[16], o1[16];
    #pragma unroll
    for (int d = 0; d < 16; ++d) {
        o0[d] = make_float4(0.f, 0.f, 0.f, 0.f);
        o1[d] = make_float4(0.f, 0.f, 0.f, 0.f);
    }

    if (shp) {
        const int r0l = ws0 - lo;
        #pragma unroll
        for (int jj = 0; jj < 14; ++jj) {
            const float4* vr = rowptr(r0l + 2 * jj);
            const float p0 = (jj < 13) ? s0[jj] : 0.f;
            const float p1 = (jj >= 1) ? s1[jj - 1] : 0.f;
            #pragma unroll
            for (int d = 0; d < 16; ++d) {
                const float4 v4 = vr[d];
                o0[d].x = fmaf(p0, v4.x, o0[d].x); o0[d].y = fmaf(p0, v4.y, o0[d].y);
                o0[d].z = fmaf(p0, v4.z, o0[d].z); o0[d].w = fmaf(p0, v4.w, o0[d].w);
                o1[d].x = fmaf(p1, v4.x, o1[d].x); o1[d].y = fmaf(p1, v4.y, o1[d].y);
                o1[d].z = fmaf(p1, v4.z, o1[d].z); o1[d].w = fmaf(p1, v4.w, o1[d].w);
            }
        }
    } else {
        const int rA = ws0 - lo, rB = ws1 - lo;
        #pragma unroll
        for (int j = 0; j < KS; ++j) {
            const float4* vr = rowptr(rA + 2 * j);
            const float p = s0[j];
            #pragma unroll
            for (int d = 0; d < 16; ++d) {
                const float4 v4 = vr[d];
                o0[d].x = fmaf(p, v4.x, o0[d].x); o0[d].y = fmaf(p, v4.y, o0[d].y);
                o0[d].z = fmaf(p, v4.z, o0[d].z); o0[d].w = fmaf(p, v4.w, o0[d].w);
            }
        }
        #pragma unroll
        for (int j = 0; j < KS; ++j) {
            const float4* vr = rowptr(rB + 2 * j);
            const float p = s1[j];
            #pragma unroll
            for (int d = 0; d < 16; ++d) {
                const float4 v4 = vr[d];
                o1[d].x = fmaf(p, v4.x, o1[d].x); o1[d].y = fmaf(p, v4.y, o1[d].y);
                o1[d].z = fmaf(p, v4.z, o1[d].z); o1[d].w = fmaf(p, v4.w, o1[d].w);
            }
        }
    }

    // ---- write out [B, L, H*DH] ----
    {
        float* op0 = out + ((size_t)b * LL + i0) * DIM + h * DH;
        float* op1 = out + ((size_t)b * LL + i1) * DIM + h * DH;
        #pragma unroll
        for (int d = 0; d < 16; ++d) {
            float4 r0 = o0[d];
            r0.x *= rinv0; r0.y *= rinv0; r0.z *= rinv0; r0.w *= rinv0;
            *(float4*)&op0[d << 2] = r0;
            float4 r1 = o1[d];
            r1.x *= rinv1; r1.y *= rinv1; r1.z *= rinv1; r1.w *= rinv1;
            *(float4*)&op1[d << 2] = r1;
        }
    }
}

// ---------------------------------------------------------------------------
extern "C" void kernel_launch(void* const* d_in, const int* in_sizes, int n_in,
                              void* d_out, int out_size)
{
    const float* hs  = (const float*)d_in[0];
    const float* Wq  = (const float*)d_in[1];
    const float* bq  = (const float*)d_in[2];
    const float* Wk  = (const float*)d_in[3];
    const float* bk  = (const float*)d_in[4];
    const float* Wv  = (const float*)d_in[5];
    const float* bv  = (const float*)d_in[6];
    const float* rpb = (const float*)d_in[7];
    float* out = (float*)d_out;

    const int gemm_smem = NSTG * STAGE_B;   // 96KB
    cudaFuncSetAttribute(qkv_mma_gemm, cudaFuncAttributeMaxDynamicSharedMemorySize, gemm_smem);
    const int attn_smem = SMW * 4;          // 76240 B
    cudaFuncSetAttribute(na1d_kernel, cudaFuncAttributeMaxDynamicSharedMemorySize, attn_smem);

    convert_a_kernel<<<32768, 256>>>(hs);
    convert_w_kernel<<<dim3(16, 16, 3), dim3(32, 8)>>>(Wq, Wk, Wv);
    qkv_mma_gemm<<<dim3(12, 512), 256, gemm_smem>>>(bq, bk, bv);
    na1d_kernel<<<dim3(LL / QT2, BB * NH), 128, attn_smem>>>(rpb, out);
}

// round 14
// speedup vs baseline: 1.2361x; 1.2361x over previous
#include <cuda_runtime.h>
#include <cuda_fp16.h>
#include <cstdint>

#define BB   8
#define LL   8192
#define DIM  512
#define NH   8
#define DH   64
#define KS   13
#define NS   6
#define DIL  2

// ---------------------------------------------------------------------------
// Device scratch (static only)
// ---------------------------------------------------------------------------
__device__ float  g_q [(size_t)BB * NH * LL * DH];   // fp32 (precision anchor)
__device__ __half g_kh[(size_t)BB * NH * LL * DH];   // fp16 K
__device__ __half g_vh[(size_t)BB * NH * LL * DH];   // fp16 V
__device__ __half g_ah[(size_t)BB * LL * DIM];       // hidden fp16 [M,K]
__device__ __half g_wh[3][DIM * DIM];                // W^T fp16  [N,K]

// ---------------------------------------------------------------------------
// Baseline-PTX helpers
// ---------------------------------------------------------------------------
__device__ __forceinline__ uint32_t smem_u32(const void* p) {
    uint32_t a;
    asm("{ .reg .u64 t; cvta.to.shared.u64 t, %1; cvt.u32.u64 %0, t; }" : "=r"(a) : "l"(p));
    return a;
}
__device__ __forceinline__ void cp_async16(uint32_t saddr, const void* gptr) {
    asm volatile("cp.async.cg.shared.global [%0], [%1], 16;"
                 :: "r"(saddr), "l"(__cvta_generic_to_global(gptr)) : "memory");
}
#define CP_COMMIT() asm volatile("cp.async.commit_group;" ::: "memory")
#define CP_WAIT(n)  asm volatile("cp.async.wait_group %0;" :: "n"(n) : "memory")

__device__ __forceinline__ void ldsm_x4(uint32_t* r, uint32_t addr) {
    asm volatile("ldmatrix.sync.aligned.m8n8.x4.shared.b16 {%0,%1,%2,%3}, [%4];"
                 : "=r"(r[0]), "=r"(r[1]), "=r"(r[2]), "=r"(r[3]) : "r"(addr));
}
__device__ __forceinline__ void ldsm_x2(uint32_t* r, uint32_t addr) {
    asm volatile("ldmatrix.sync.aligned.m8n8.x2.shared.b16 {%0,%1}, [%2];"
                 : "=r"(r[0]), "=r"(r[1]) : "r"(addr));
}
__device__ __forceinline__ void mma16816(float* c, const uint32_t* a, const uint32_t* b) {
    asm volatile("mma.sync.aligned.m16n8k16.row.col.f32.f16.f16.f32 "
                 "{%0,%1,%2,%3}, {%4,%5,%6,%7}, {%8,%9}, {%0,%1,%2,%3};"
                 : "+f"(c[0]), "+f"(c[1]), "+f"(c[2]), "+f"(c[3])
                 : "r"(a[0]), "r"(a[1]), "r"(a[2]), "r"(a[3]), "r"(b[0]), "r"(b[1]));
}

// ---------------------------------------------------------------------------
// Convert hidden states fp32 -> fp16
// ---------------------------------------------------------------------------
__global__ void convert_a_kernel(const float* __restrict__ A) {
    size_t i = ((size_t)blockIdx.x * 256 + threadIdx.x) * 4;
    float4 x = *(const float4*)(A + i);
    union { __half b[4]; uint2 u; } ph;
    ph.b[0] = __float2half_rn(x.x);
    ph.b[1] = __float2half_rn(x.y);
    ph.b[2] = __float2half_rn(x.z);
    ph.b[3] = __float2half_rn(x.w);
    *(uint2*)(g_ah + i) = ph.u;
}

// ---------------------------------------------------------------------------
// Transpose W [K,N] -> W^T [N,K] fp16
// ---------------------------------------------------------------------------
__global__ void convert_w_kernel(const float* __restrict__ Wq,
                                 const float* __restrict__ Wk,
                                 const float* __restrict__ Wv) {
    const int z = blockIdx.z;
    const float* W = (z == 0) ? Wq : ((z == 1) ? Wk : Wv);
    __shared__ float t[32][33];
    const int n0 = blockIdx.x * 32, k0 = blockIdx.y * 32;
    #pragma unroll
    for (int j = 0; j < 32; j += 8)
        t[threadIdx.y + j][threadIdx.x] = W[(size_t)(k0 + threadIdx.y + j) * DIM + n0 + threadIdx.x];
    __syncthreads();
    #pragma unroll
    for (int j = 0; j < 32; j += 8) {
        float v = t[threadIdx.x][threadIdx.y + j];
        size_t o = (size_t)(n0 + threadIdx.y + j) * DIM + k0 + threadIdx.x;
        g_wh[z][o] = __float2half_rn(v);
    }
}

// ---------------------------------------------------------------------------
// HMMA fp16 GEMM (1-term): mainloop unchanged from R12.
// Epilogue: q -> fp32 g_q; k,v -> fp16 g_kh/g_vh (halves store traffic).
// ---------------------------------------------------------------------------
#define TILE_B   16384
#define STAGE_B  (2 * TILE_B)     // 32KB
#define NSTG     3
#define KSTAGES  8                // 512 / 64

__global__ void __launch_bounds__(256)
qkv_mma_gemm(const float* __restrict__ bq, const float* __restrict__ bk,
             const float* __restrict__ bv)
{
    extern __shared__ __align__(1024) char dsm[];
    __shared__ float s_bias[128];

    const int tid  = threadIdx.x;
    const int wid  = tid >> 5;
    const int lane = tid & 31;
    const int wm   = wid >> 2;
    const int wn   = wid & 3;
    const int nt   = blockIdx.x & 3;
    const int z    = blockIdx.x >> 2;
    const int mt   = blockIdx.y;

    const uint32_t sbase = smem_u32(dsm);

    const float* bias = (z == 0) ? bq : ((z == 1) ? bk : bv);
    const float scale = (z == 0) ? 0.125f : 1.0f;
    const __half* srcs[2] = { g_ah + (size_t)mt * 128 * DIM,
                              g_wh[z] + (size_t)nt * 128 * DIM };

    if (tid < 128) s_bias[tid] = bias[nt * 128 + tid];

    auto load_stage = [&](int kt, int buf) {
        const uint32_t sb = sbase + (uint32_t)buf * STAGE_B;
        #pragma unroll
        for (int tile = 0; tile < 2; ++tile) {
            const __half* src = srcs[tile] + kt * 64;
            #pragma unroll
            for (int it = 0; it < 4; ++it) {
                const int c = it * 256 + tid;
                const int r = c >> 3, j = c & 7;
                const uint32_t soff = sb + (uint32_t)tile * TILE_B +
                                      (uint32_t)r * 128 + (uint32_t)((j ^ (r & 7)) << 4);
                cp_async16(soff, src + (size_t)r * DIM + j * 8);
            }
        }
        CP_COMMIT();
    };

    float acc[4][4][4];
    #pragma unroll
    for (int mi = 0; mi < 4; ++mi)
        #pragma unroll
        for (int ni = 0; ni < 4; ++ni)
            #pragma unroll
            for (int q = 0; q < 4; ++q) acc[mi][ni][q] = 0.f;

    load_stage(0, 0);
    load_stage(1, 1);

    for (int kt = 0; kt < KSTAGES; ++kt) {
        if (kt < KSTAGES - 1) { CP_WAIT(1); } else { CP_WAIT(0); }
        __syncthreads();
        if (kt + 2 < KSTAGES) load_stage(kt + 2, (kt + 2) % NSTG);

        const uint32_t sb = sbase + (uint32_t)(kt % NSTG) * STAGE_B;
        const uint32_t aH = sb, bH = sb + TILE_B;

        const int arow = wm * 64 + (lane & 15);
        const int ahalf = lane >> 4;
        const int brow = wn * 32 + (lane & 7);
        const int bhalf = (lane >> 3) & 1;

        #pragma unroll
        for (int ks = 0; ks < 4; ++ks) {
            uint32_t bhf[4][2];
            #pragma unroll
            for (int ni = 0; ni < 4; ++ni) {
                const int r = brow + ni * 8;
                const int j = ks * 2 + bhalf;
                const uint32_t off = (uint32_t)r * 128 + (uint32_t)((j ^ (r & 7)) << 4);
                ldsm_x2(bhf[ni], bH + off);
            }
            #pragma unroll
            for (int mi = 0; mi < 4; ++mi) {
                const int r = arow + mi * 16;
                const int j = ks * 2 + ahalf;
                const uint32_t off = (uint32_t)r * 128 + (uint32_t)((j ^ (r & 7)) << 4);
                uint32_t ahf[4];
                ldsm_x4(ahf, aH + off);
                #pragma unroll
                for (int ni = 0; ni < 4; ++ni)
                    mma16816(acc[mi][ni], ahf, bhf[ni]);
            }
        }
    }

    const int g = lane >> 2, tig = lane & 3;
    #pragma unroll
    for (int mi = 0; mi < 4; ++mi) {
        #pragma unroll
        for (int half = 0; half < 2; ++half) {
            const int m = mt * 128 + wm * 64 + mi * 16 + g + half * 8;
            const int b = m >> 13;
            const int l = m & (LL - 1);
            #pragma unroll
            for (int ni = 0; ni < 4; ++ni) {
                const int nl = wn * 32 + ni * 8 + 2 * tig;
                const int n  = nt * 128 + nl;
                const int h  = n >> 6, d = n & 63;
                const size_t o = (((size_t)b * NH + h) * LL + l) * DH + d;
                float2 r2;
                r2.x = (acc[mi][ni][half * 2 + 0] + s_bias[nl + 0]) * scale;
                r2.y = (acc[mi][ni][half * 2 + 1] + s_bias[nl + 1]) * scale;
                if (z == 0) {
                    *(float2*)&g_q[o] = r2;
                } else {
                    __half* hp = (z == 1) ? g_kh : g_vh;
                    *(__half2*)&hp[o] = __floats2half2_rn(r2.x, r2.y);
                }
            }
        }
    }
}

// ---------------------------------------------------------------------------
// NA1D attention — R12 structure (1 query/thread, 128q/CTA), fp16 K/V tiles.
// Row = 64 halves = 32 words, stride 36 words (144B):
//   score-phase lane banks (4*lane + 4d) mod 32 -> conflict-free;
//   staging stores contiguous 128B per 8 lanes -> conflict-free.
// ---------------------------------------------------------------------------
#define QT    128
#define SPAN  152
#define PADW  36

__global__ void __launch_bounds__(128, 4)
na1d_kernel(const float* __restrict__ rpb, float* __restrict__ out)
{
    __shared__ uint32_t kvs[SPAN * PADW];   // 21888 B
    __shared__ float s_rpb[2 * KS - 1];

    const int tid = threadIdx.x;
    const int bh  = blockIdx.y;
    const int b   = bh >> 3;
    const int h   = bh & 7;
    const int l0  = blockIdx.x << 7;
    const int i   = l0 + tid;

    if (tid < 2 * KS - 1) s_rpb[tid] = rpb[h * (2 * KS - 1) + tid];

    int ws, ps;
    if (i < NS * DIL) {
        ws = i & 1;
        ps = (KS - 1) - (i >> 1);
    } else if (i + NS * DIL >= LL) {
        ws = LL - KS * DIL + (i & 1);
        ps = (LL - 1 - i) >> 1;
    } else {
        ws = i - NS * DIL;
        ps = NS;
    }

    const int lo = (l0 >= NS * DIL) ? (l0 - NS * DIL) : 0;
    const int himax = l0 + QT - 1 + NS * DIL;
    const int hi = (himax <= LL - 1) ? himax : (LL - 1);
    const int nrows = hi - lo + 1;
    const int nu4 = nrows * 8;              // 8 uint4 chunks per row
    const int r0 = ws - lo;
    const size_t base = (size_t)bh * LL * DH;

    // ---- stage K tile (fp16) ----
    {
        const uint4* src = (const uint4*)(g_kh + base + (size_t)lo * DH);
        for (int tt = tid; tt < nu4; tt += QT) {
            const int r = tt >> 3, c = tt & 7;
            *(uint4*)&kvs[r * PADW + c * 4] = src[tt];
        }
    }

    // ---- q into registers (fp32) ----
    float q[64];
    {
        const float4* qp = (const float4*)(g_q + base + (size_t)i * DH);
        #pragma unroll
        for (int d = 0; d < 16; ++d) {
            const float4 v = qp[d];
            q[d * 4 + 0] = v.x; q[d * 4 + 1] = v.y;
            q[d * 4 + 2] = v.z; q[d * 4 + 3] = v.w;
        }
    }
    __syncthreads();

    // ---- scores ----
    float sc[KS];
    #pragma unroll
    for (int j = 0; j < KS; ++j) {
        const uint4* kr = (const uint4*)&kvs[(r0 + DIL * j) * PADW];
        float s = 0.f;
        #pragma unroll
        for (int c = 0; c < 8; ++c) {
            const uint4 kk = kr[c];
            const float2 f0 = __half22float2(*(const __half2*)&kk.x);
            const float2 f1 = __half22float2(*(const __half2*)&kk.y);
            const float2 f2 = __half22float2(*(const __half2*)&kk.z);
            const float2 f3 = __half22float2(*(const __half2*)&kk.w);
            s = fmaf(q[c * 8 + 0], f0.x, s); s = fmaf(q[c * 8 + 1], f0.y, s);
            s = fmaf(q[c * 8 + 2], f1.x, s); s = fmaf(q[c * 8 + 3], f1.y, s);
            s = fmaf(q[c * 8 + 4], f2.x, s); s = fmaf(q[c * 8 + 5], f2.y, s);
            s = fmaf(q[c * 8 + 6], f3.x, s); s = fmaf(q[c * 8 + 7], f3.y, s);
        }
        sc[j] = s + s_rpb[ps + j];
    }

    // ---- softmax ----
    float mx = sc[0];
    #pragma unroll
    for (int j = 1; j < KS; ++j) mx = fmaxf(mx, sc[j]);
    float sum = 0.f;
    #pragma unroll
    for (int j = 0; j < KS; ++j) { sc[j] = __expf(sc[j] - mx); sum += sc[j]; }
    const float rinv = 1.f / sum;

    __syncthreads();

    // ---- stage V tile (fp16, same buffer) ----
    {
        const uint4* src = (const uint4*)(g_vh + base + (size_t)lo * DH);
        for (int tt = tid; tt < nu4; tt += QT) {
            const int r = tt >> 3, c = tt & 7;
            *(uint4*)&kvs[r * PADW + c * 4] = src[tt];
        }
    }
    __syncthreads();

    // ---- weighted sum of V ----
    float o[64];
    #pragma unroll
    for (int d = 0; d < 64; ++d) o[d] = 0.f;

    #pragma unroll
    for (int j = 0; j < KS; ++j) {
        const float p = sc[j];
        const uint4* vr = (const uint4*)&kvs[(r0 + DIL * j) * PADW];
        #pragma unroll
        for (int c = 0; c < 8; ++c) {
            const uint4 vv = vr[c];
            const float2 f0 = __half22float2(*(const __half2*)&vv.x);
            const float2 f1 = __half22float2(*(const __half2*)&vv.y);
            const float2 f2 = __half22float2(*(const __half2*)&vv.z);
            const float2 f3 = __half22float2(*(const __half2*)&vv.w);
            o[c * 8 + 0] = fmaf(p, f0.x, o[c * 8 + 0]);
            o[c * 8 + 1] = fmaf(p, f0.y, o[c * 8 + 1]);
            o[c * 8 + 2] = fmaf(p, f1.x, o[c * 8 + 2]);
            o[c * 8 + 3] = fmaf(p, f1.y, o[c * 8 + 3]);
            o[c * 8 + 4] = fmaf(p, f2.x, o[c * 8 + 4]);
            o[c * 8 + 5] = fmaf(p, f2.y, o[c * 8 + 5]);
            o[c * 8 + 6] = fmaf(p, f3.x, o[c * 8 + 6]);
            o[c * 8 + 7] = fmaf(p, f3.y, o[c * 8 + 7]);
        }
    }

    // ---- write out [B, L, H*DH] ----
    float* op = out + ((size_t)b * LL + i) * DIM + h * DH;
    #pragma unroll
    for (int d = 0; d < 16; ++d) {
        float4 r;
        r.x = o[d * 4 + 0] * rinv; r.y = o[d * 4 + 1] * rinv;
        r.z = o[d * 4 + 2] * rinv; r.w = o[d * 4 + 3] * rinv;
        *(float4*)&op[d << 2] = r;
    }
}

// ---------------------------------------------------------------------------
extern "C" void kernel_launch(void* const* d_in, const int* in_sizes, int n_in,
                              void* d_out, int out_size)
{
    const float* hs  = (const float*)d_in[0];
    const float* Wq  = (const float*)d_in[1];
    const float* bq  = (const float*)d_in[2];
    const float* Wk  = (const float*)d_in[3];
    const float* bk  = (const float*)d_in[4];
    const float* Wv  = (const float*)d_in[5];
    const float* bv  = (const float*)d_in[6];
    const float* rpb = (const float*)d_in[7];
    float* out = (float*)d_out;

    const int gemm_smem = NSTG * STAGE_B;   // 96KB
    cudaFuncSetAttribute(qkv_mma_gemm, cudaFuncAttributeMaxDynamicSharedMemorySize, gemm_smem);

    convert_a_kernel<<<32768, 256>>>(hs);
    convert_w_kernel<<<dim3(16, 16, 3), dim3(32, 8)>>>(Wq, Wk, Wv);
    qkv_mma_gemm<<<dim3(12, 512), 256, gemm_smem>>>(bq, bk, bv);
    na1d_kernel<<<dim3(LL / QT, BB * NH), 128>>>(rpb, out);
}